// round 6
// baseline (speedup 1.0000x reference)
#include <cuda_runtime.h>
#include <cuda_bf16.h>

#define SEQ   4096
#define DIM   512
#define DIM1  513
#define PI_F  3.14159265358979f

// Output-vectorized concat with vectorized input gather.
// Each thread produces one aligned float4 of the flat [B*S*513] output.
// Fast path (window fully inside the 512 copy columns): 1-2 aligned LDG.128
// + static shuffle by d = c&3. Slow path (window touches pe col 512): scalar.
__global__ __launch_bounds__(256) void pe_concat_kernel(
    const float* __restrict__ in,
    const int*   __restrict__ lengths,
    float*       __restrict__ out,
    int n4)
{
    int i4 = blockIdx.x * blockDim.x + threadIdx.x;
    if (i4 >= n4) return;

    int base = i4 * 4;          // flat output element index
    int r = base / DIM1;        // row = b*4096 + s  (const-div -> mulhi)
    int c = base - r * DIM1;    // column in [0, 513)

    float4 o;

    if (c <= DIM - 4) {
        // window [c, c+3] entirely within the copy region of row r
        const float4* in4 = reinterpret_cast<const float4*>(in);
        int w = (r * DIM + c) >> 2;   // aligned word index (r*512 % 4 == 0)
        int d = c & 3;

        float4 lo = __ldg(in4 + w);
        if (d == 0) {
            o = lo;
        } else {
            float4 hi = __ldg(in4 + w + 1);
            if (d == 1)      { o.x = lo.y; o.y = lo.z; o.z = lo.w; o.w = hi.x; }
            else if (d == 2) { o.x = lo.z; o.y = lo.w; o.z = hi.x; o.w = hi.y; }
            else             { o.x = lo.w; o.y = hi.x; o.z = hi.y; o.w = hi.z; }
        }
    } else {
        // window straddles pe column 512 (and possibly the next row)
        float v[4];
#pragma unroll
        for (int j = 0; j < 4; j++) {
            float val;
            if (c < DIM) {
                val = __ldg(in + r * DIM + c);
            } else {
                int b = r >> 12;            // row / 4096
                int s = r & (SEQ - 1);      // row % 4096
                float fl   = (float)__ldg(lengths + b);
                float safe = fmaxf(fl, 1.0f);
                val = ((float)s < fl) ? __cosf(((float)s / safe) * PI_F) : 0.0f;
            }
            v[j] = val;
            if (++c == DIM1) { c = 0; ++r; }
        }
        o.x = v[0]; o.y = v[1]; o.z = v[2]; o.w = v[3];
    }

    reinterpret_cast<float4*>(out)[i4] = o;
}

extern "C" void kernel_launch(void* const* d_in, const int* in_sizes, int n_in,
                              void* d_out, int out_size)
{
    const float* in      = (const float*)d_in[0];   // [16, 4096, 512] f32
    const int*   lengths = (const int*)  d_in[1];   // [16] i32
    float*       out     = (float*)d_out;           // [16, 4096, 513] f32

    int n4 = out_size / 4;                          // 33,619,968 / 4
    int threads = 256;
    int blocks  = (n4 + threads - 1) / threads;
    pe_concat_kernel<<<blocks, threads>>>(in, lengths, out, n4);
}

// round 7
// speedup vs baseline: 1.0403x; 1.0403x over previous
#include <cuda_runtime.h>
#include <cuda_bf16.h>

#define SEQ   4096
#define DIM   512
#define DIM1  513
#define PI_F  3.14159265358979f

// Output-vectorized concat, ILP=4: each thread produces 4 aligned float4s of
// the flat [B*S*513] output, spaced blockDim apart so every LDG/STG stays
// warp-coalesced. All 16 input loads are independent -> high MLP.
//
// Index identity per group (base=i4*4, r=base/513, c=base-513r, A=r*512+c):
//   output elem j in [0,4):  pe-channel iff j == 512-c
//   input addr             :  A + j - (c+j >= 513)
// (a window never spans more than one row boundary since 513 > 4)
__global__ __launch_bounds__(256) void pe_concat_kernel(
    const float* __restrict__ in,
    const int*   __restrict__ lengths,
    float*       __restrict__ out)
{
    const int i4_0 = blockIdx.x * 1024 + threadIdx.x;

    float4 o[4];
#pragma unroll
    for (int g = 0; g < 4; g++) {
        const int i4   = i4_0 + g * 256;
        const int base = i4 * 4;
        const int r    = base / DIM1;            // const-div -> mulhi
        const int c    = base - r * DIM1;
        const int kpe  = DIM - c;                // j-index of pe elem (may be >=4)
        const float* p = in + r * DIM + c;       // A

        float v[4];
#pragma unroll
        for (int j = 0; j < 4; j++) {
            const int adj = (j > kpe) ? 1 : 0;   // c+j >= 513
            v[j] = (j == kpe) ? 0.0f : __ldg(p + j - adj);
        }

        if (kpe < 4) {                           // ~0.78% of groups
            const int b = r >> 12;               // row / 4096
            const int s = r & (SEQ - 1);         // row % 4096
            const float fl   = (float)__ldg(lengths + b);
            const float safe = fmaxf(fl, 1.0f);
            v[kpe] = ((float)s < fl) ? __cosf(((float)s / safe) * PI_F) : 0.0f;
        }

        o[g].x = v[0]; o[g].y = v[1]; o[g].z = v[2]; o[g].w = v[3];
    }

    float4* out4 = reinterpret_cast<float4*>(out);
#pragma unroll
    for (int g = 0; g < 4; g++)
        out4[i4_0 + g * 256] = o[g];
}

extern "C" void kernel_launch(void* const* d_in, const int* in_sizes, int n_in,
                              void* d_out, int out_size)
{
    const float* in      = (const float*)d_in[0];   // [16, 4096, 512] f32
    const int*   lengths = (const int*)  d_in[1];   // [16] i32
    float*       out     = (float*)d_out;           // [16, 4096, 513] f32

    // out_size = 16*4096*513 = 33,619,968 floats = 8,404,992 float4
    //          = 8208 blocks * 1024 float4/block, exact -> no bounds checks
    (void)in_sizes; (void)n_in; (void)out_size;
    pe_concat_kernel<<<8208, 256>>>(in, lengths, out);
}